// round 8
// baseline (speedup 1.0000x reference)
#include <cuda_runtime.h>
#include <math.h>

#define Bmax 1024
#define Nn   100
#define Hh   128
#define NHEADS 8
#define HD   16
#define NP4  26          // padded node count in float4 (104 floats)
#define NPF  104
#define K2S  132         // K2 row stride (floats)
#define JALL 384
#define NEGV -1000000000.0f

// ---- device scratch (no cudaMalloc allowed) ----
__device__ float g_Wcat[Hh * 512];             // [k][j]: Wk^T | Wv^T | Wk2^T@Wo | Wqf[:, :128]^T
__device__ float g_Wqf [Hh * (Hh + 1)];        // Wq @ fc_w   (128 x 129)
__device__ float g_Wq1 [Hh * Hh];              // Wq @ fc1_w  (128 x 128)
__device__ float g_qpool[Bmax * Hh];           // (pool @ fc1_w^T) @ Wq^T
__device__ float g_EncProj[(size_t)Bmax * 256 * Nn];   // [b][j][n]: K | V   (j<256)
__device__ float g_K2Wt[(size_t)Bmax * Nn * Hh];       // [b][n][h]  (K2@Wo) row-major
__device__ float g_QP  [(size_t)Bmax * Nn * Hh];       // [b][n][h]  enc @ Wqf[:, :128]^T

// =====================================================================
// Kernel 1: combine small weight matrices
// =====================================================================
__global__ void weights_kernel(const float* __restrict__ fc_w,
                               const float* __restrict__ fc1_w,
                               const float* __restrict__ Wq,
                               const float* __restrict__ Wk,
                               const float* __restrict__ Wv,
                               const float* __restrict__ Wo,
                               const float* __restrict__ Wk2)
{
    int bid = blockIdx.x, t = threadIdx.x;   // t = 0..127
    if (bid < 512) {
        int j = bid;
        float v;
        if (j < 128) {
            v = Wk[j * 128 + t];
        } else if (j < 256) {
            v = Wv[(j - 128) * 128 + t];
        } else if (j < 384) {
            int jp = j - 256;
            float s = 0.f;
            for (int h = 0; h < 128; h++) s += Wk2[h * 128 + t] * Wo[h * 128 + jp];
            v = s;
        } else {
            int hq = j - 384;          // Wqf[hq][t]
            float s = 0.f;
            for (int jj = 0; jj < 128; jj++) s += Wq[hq * 128 + jj] * fc_w[jj * 129 + t];
            v = s;
        }
        g_Wcat[t * 512 + j] = v;
    } else if (bid < 640) {
        int i = bid - 512;
        for (int k = t; k < 129; k += 128) {
            float s = 0.f;
            for (int j = 0; j < 128; j++) s += Wq[i * 128 + j] * fc_w[j * 129 + k];
            g_Wqf[i * 129 + k] = s;
        }
    } else {
        int i = bid - 640;
        float s = 0.f;
        for (int j = 0; j < 128; j++) s += Wq[i * 128 + j] * fc1_w[j * 128 + t];
        g_Wq1[i * 128 + t] = s;
    }
}

// =====================================================================
// Kernel 2: qpool[b][h] = sum_k Wq1[h][k] * pool[b][k]
// =====================================================================
__global__ void qpool_kernel(const float* __restrict__ pool)
{
    int b = blockIdx.x, h = threadIdx.x;
    float s = 0.f;
    for (int k = 0; k < 128; k++) s += g_Wq1[h * 128 + k] * pool[b * 128 + k];
    g_qpool[b * 128 + h] = s;
}

// =====================================================================
// Kernel 3: projections. 512 threads; thread j owns weight column j.
// j<256  -> g_EncProj[b][j][n]   (K | V, n-contiguous)
// j<384  -> g_K2Wt[b][n][j-256]  (row-major)
// j<512  -> g_QP[b][n][j-384]    (row-major)
// =====================================================================
__global__ __launch_bounds__(512, 1)
void encproj_kernel(const float* __restrict__ enc)
{
    extern __shared__ float As[];            // [100][128]
    int b = blockIdx.x, t = threadIdx.x;
    for (int i = t; i < Nn * Hh; i += 512) As[i] = enc[(size_t)b * Nn * Hh + i];
    float w[128];
#pragma unroll
    for (int k = 0; k < 128; k++) w[k] = g_Wcat[k * 512 + t];
    __syncthreads();

    float* rowp = (t < 256) ? (g_EncProj + (size_t)b * 256 * Nn + (size_t)t * Nn) : 0;
    float* colp = (t < 384) ? (g_K2Wt + (size_t)b * Nn * Hh + (t - 256))
                            : (g_QP   + (size_t)b * Nn * Hh + (t - 384));

    for (int n0 = 0; n0 < Nn; n0 += 4) {
        float a0 = 0.f, a1 = 0.f, a2 = 0.f, a3 = 0.f;
        const float4* r0 = reinterpret_cast<const float4*>(&As[(n0 + 0) * Hh]);
        const float4* r1 = reinterpret_cast<const float4*>(&As[(n0 + 1) * Hh]);
        const float4* r2 = reinterpret_cast<const float4*>(&As[(n0 + 2) * Hh]);
        const float4* r3 = reinterpret_cast<const float4*>(&As[(n0 + 3) * Hh]);
#pragma unroll
        for (int kk = 0; kk < 32; kk++) {
            float4 x0 = r0[kk];
            a0 += x0.x * w[4*kk] + x0.y * w[4*kk+1] + x0.z * w[4*kk+2] + x0.w * w[4*kk+3];
            float4 x1 = r1[kk];
            a1 += x1.x * w[4*kk] + x1.y * w[4*kk+1] + x1.z * w[4*kk+2] + x1.w * w[4*kk+3];
            float4 x2 = r2[kk];
            a2 += x2.x * w[4*kk] + x2.y * w[4*kk+1] + x2.z * w[4*kk+2] + x2.w * w[4*kk+3];
            float4 x3 = r3[kk];
            a3 += x3.x * w[4*kk] + x3.y * w[4*kk+1] + x3.z * w[4*kk+2] + x3.w * w[4*kk+3];
        }
        if (t < 256) {
            reinterpret_cast<float4*>(rowp + n0)[0] = make_float4(a0, a1, a2, a3);
        } else {
            colp[(size_t)(n0 + 0) * Hh] = a0;
            colp[(size_t)(n0 + 1) * Hh] = a1;
            colp[(size_t)(n0 + 2) * Hh] = a2;
            colp[(size_t)(n0 + 3) * Hh] = a3;
        }
    }
}

// =====================================================================
// Kernel 4: dense vectorized persistent decoder. 512 threads, 1 blk/SM.
// =====================================================================
#define DEC_SMEM_FLOATS (Hh*NPF*2 + Nn*K2S + Nn*Hh + 128 + 128 + NHEADS*NPF + 128 + NPF + NPF + NPF + NPF + 8 + 8)
#define DEC_SMEM_BYTES  (DEC_SMEM_FLOATS * 4)

__global__ __launch_bounds__(512, 1)
void decode_kernel(const float* __restrict__ capacity,
                   const float* __restrict__ demand,
                   const int*   __restrict__ Tptr,
                   float* __restrict__ out, int ns, int B)
{
    extern __shared__ float sm[];
    float* KT    = sm;                    // [128][104] K^T
    float* VT    = KT   + Hh * NPF;       // [128][104] V^T
    float* K2s   = VT   + Hh * NPF;       // [100][132] K2W rows
    float* QPs   = K2s  + Nn * K2S;       // [100][128]
    float* qp    = QPs  + Nn * Hh;        // 128
    float* wcap  = qp   + 128;            // 128
    float* att   = wcap + 128;            // 8*104
    float* g     = att  + NHEADS * NPF;   // 128
    float* u     = g    + 128;            // 104
    float* dem   = u    + NPF;            // 104 (pads = +big)
    float* mask1 = dem  + NPF;            // 104 (pads = 1)
    float* MSK   = mask1+ NPF;            // 104 (pads = 1)
    float* misc  = MSK  + NPF;            // [0]=cap [1]=base [2]=logp [3]=invT
    int*   imisc = (int*)(misc + 8);      // [0]=idx [1]=visited

    const int b = blockIdx.x, t = threadIdx.x;
    const int w = t >> 5, lane = t & 31;
    const int h4 = t >> 2, p4 = t & 3;

    // ---- load operands ----
    const float* ep = g_EncProj + (size_t)b * 256 * Nn;
    for (int i = t; i < 256 * NPF; i += 512) {
        int j = i / NPF, n = i - j * NPF;
        sm[j * NPF + n] = (n < Nn) ? ep[j * Nn + n] : 0.f;   // KT|VT contiguous
    }
    const float* k2g = g_K2Wt + (size_t)b * Nn * Hh;
    for (int i = t; i < Nn * K2S; i += 512) {
        int n = i / K2S, h = i - n * K2S;
        K2s[i] = (h < Hh) ? k2g[n * Hh + h] : 0.f;
    }
    const float* qpg = g_QP + (size_t)b * Nn * Hh;
    for (int i = t; i < Nn * Hh; i += 512) QPs[i] = qpg[i];
    if (t < 128) {
        qp[t]   = g_qpool[b * 128 + t];
        wcap[t] = g_Wqf[t * 129 + 128];
    }
    if (t < NPF) {
        dem[t]   = (t < Nn) ? demand[b * Nn + t] : 3.0e38f;
        mask1[t] = (t < Nn) ? 0.f : 1.f;
    }
    if (t == 0) {
        float c = capacity[b];
        misc[0] = c; misc[1] = capacity[0]; misc[2] = 0.f;
        misc[3] = 1.0f / (float)(*Tptr);
        imisc[0] = 0; imisc[1] = 0;
    }
    __syncthreads();

    // ---- initial mask (idx=0, mask1=0) : warp 0 ----
    if (w == 0) {
        float capc = misc[0];
        float4 dm = reinterpret_cast<const float4*>(dem)[lane < NP4 ? lane : 0];
        float4 m1 = reinterpret_cast<const float4*>(mask1)[lane < NP4 ? lane : 0];
        float4 mk;
        mk.x = (m1.x > 0.f || dm.x > capc) ? 1.f : 0.f;
        mk.y = (m1.y > 0.f || dm.y > capc) ? 1.f : 0.f;
        mk.z = (m1.z > 0.f || dm.z > capc) ? 1.f : 0.f;
        mk.w = (m1.w > 0.f || dm.w > capc) ? 1.f : 0.f;
        // all customers (n=1..99) masked?
        bool mine = true;
        if (lane < NP4) {
            if (lane > 0) mine = (mk.x > 0.f) && (mk.y > 0.f) && (mk.z > 0.f) && (mk.w > 0.f);
            else          mine = (mk.y > 0.f) && (mk.z > 0.f) && (mk.w > 0.f);
        }
        bool allc = __all_sync(0xffffffffu, mine);
        if (lane == 0) mk.x = allc ? 0.f : 1.f;   // go_depot true at step 0
        if (lane < NP4) reinterpret_cast<float4*>(MSK)[lane] = mk;
    }
    __syncthreads();

    const float4* KT4  = reinterpret_cast<const float4*>(KT);
    const float4* VT4  = reinterpret_cast<const float4*>(VT);
    const float4* MSK4 = reinterpret_cast<const float4*>(MSK);
    float4* att4 = reinterpret_cast<float4*>(att);

    for (int step = 0; step < ns; step++) {
        // ==== R1: q chunk + dense scores + softmax (warp w = head w) ====
        if (w < NHEADS) {
            int sidx = imisc[0];
            float capc = misc[0];
            float qd = 0.f;
            if (lane < HD) {
                int hh = w * HD + lane;
                qd = qp[hh] + QPs[sidx * Hh + hh] + capc * wcap[hh];
            }
            float4 acc = make_float4(0.f, 0.f, 0.f, 0.f);
            const int li = (lane < NP4) ? lane : 0;
            const float4* kb = KT4 + (w * HD) * NP4;
#pragma unroll
            for (int d = 0; d < HD; d++) {
                float qv = __shfl_sync(0xffffffffu, qd, d);
                float4 kv = kb[d * NP4 + li];
                acc.x += qv * kv.x; acc.y += qv * kv.y;
                acc.z += qv * kv.z; acc.w += qv * kv.w;
            }
            float4 mv = MSK4[li];
            float4 v;
            v.x = (lane < NP4 && mv.x == 0.f) ? acc.x * 0.25f : NEGV;
            v.y = (lane < NP4 && mv.y == 0.f) ? acc.y * 0.25f : NEGV;
            v.z = (lane < NP4 && mv.z == 0.f) ? acc.z * 0.25f : NEGV;
            v.w = (lane < NP4 && mv.w == 0.f) ? acc.w * 0.25f : NEGV;
            float m = fmaxf(fmaxf(v.x, v.y), fmaxf(v.z, v.w));
#pragma unroll
            for (int off = 16; off; off >>= 1) m = fmaxf(m, __shfl_xor_sync(0xffffffffu, m, off));
            float4 e;
            e.x = expf(v.x - m); e.y = expf(v.y - m);
            e.z = expf(v.z - m); e.w = expf(v.w - m);
            float ss = e.x + e.y + e.z + e.w;
#pragma unroll
            for (int off = 16; off; off >>= 1) ss += __shfl_xor_sync(0xffffffffu, ss, off);
            float inv = 1.f / ss;
            if (lane < NP4)
                att4[w * NP4 + lane] = make_float4(e.x*inv, e.y*inv, e.z*inv, e.w*inv);
        }
        __syncthreads();

        // ==== R2: g[h] = attn_head(h) · V[h] (dense float4) ====
        {
            const float4* ap = att4 + (h4 >> 4) * NP4;
            const float4* vp = VT4 + h4 * NP4;
            float sg = 0.f;
#pragma unroll 2
            for (int j = p4; j < NP4; j += 4) {
                float4 a = ap[j], vv = vp[j];
                sg += a.x*vv.x + a.y*vv.y + a.z*vv.z + a.w*vv.w;
            }
            sg += __shfl_xor_sync(0xffffffffu, sg, 1);
            sg += __shfl_xor_sync(0xffffffffu, sg, 2);
            if (p4 == 0) g[h4] = sg;
        }
        __syncthreads();

        // ==== R3: dense u[n] = mask ? NEG : CLIP*tanh(g·K2[n]/sqrt(H)) ====
        {
            int n = h4;                         // 0..127
            int nc = (n < Nn) ? n : 0;
            const float4* kp = reinterpret_cast<const float4*>(K2s + nc * K2S) + p4 * 8;
            const float4* gp = reinterpret_cast<const float4*>(g) + p4 * 8;
            float su = 0.f;
#pragma unroll
            for (int r = 0; r < 8; r++) {
                float4 kv = kp[r], gv = gp[r];
                su += kv.x*gv.x + kv.y*gv.y + kv.z*gv.z + kv.w*gv.w;
            }
            su += __shfl_xor_sync(0xffffffffu, su, 1);
            su += __shfl_xor_sync(0xffffffffu, su, 2);
            if (p4 == 0 && n < NPF) {
                float val = (n < Nn && MSK[n] == 0.f)
                          ? 10.f * tanhf(su * 0.08838834764831845f) : NEGV;
                u[n] = val;
            }
        }
        __syncthreads();

        // ==== R4: argmax + log-softmax + state + mask update (warp 0) ====
        if (w == 0) {
            float invT = misc[3];
            const int li = (lane < NP4) ? lane : 0;
            float4 uv = reinterpret_cast<const float4*>(u)[li];
            float4 v;
            v.x = (lane < NP4) ? uv.x * invT : NEGV;
            v.y = (lane < NP4) ? uv.y * invT : NEGV;
            v.z = (lane < NP4) ? uv.z * invT : NEGV;
            v.w = (lane < NP4) ? uv.w * invT : NEGV;
            int n0 = lane * 4;
            float best = v.x; int bn = n0;
            if (v.y > best) { best = v.y; bn = n0 + 1; }
            if (v.z > best) { best = v.z; bn = n0 + 2; }
            if (v.w > best) { best = v.w; bn = n0 + 3; }
#pragma unroll
            for (int off = 16; off; off >>= 1) {
                float ov = __shfl_xor_sync(0xffffffffu, best, off);
                int   on = __shfl_xor_sync(0xffffffffu, bn,   off);
                if (ov > best || (ov == best && on < bn)) { best = ov; bn = on; }
            }
            float ss = expf(v.x - best) + expf(v.y - best)
                     + expf(v.z - best) + expf(v.w - best);
#pragma unroll
            for (int off = 16; off; off >>= 1) ss += __shfl_xor_sync(0xffffffffu, ss, off);

            if (lane == 0) {
                int idx = bn;
                imisc[0] = idx;
                if (imisc[1] < Nn - 1) misc[2] += -logf(ss);
                out[(size_t)b * ns + step] = (float)idx;
                float c = (idx == 0) ? misc[1] : misc[0] - dem[idx];
                misc[0] = c;
                if (idx > 0 && mask1[idx] == 0.f) { mask1[idx] = 1.f; imisc[1] += 1; }
            }
            __syncwarp();
            // mask rebuild
            float capc = misc[0];
            int idx = imisc[0];
            float4 dm = reinterpret_cast<const float4*>(dem)[li];
            float4 m1 = reinterpret_cast<const float4*>(mask1)[li];
            float4 mk;
            mk.x = (m1.x > 0.f || dm.x > capc) ? 1.f : 0.f;
            mk.y = (m1.y > 0.f || dm.y > capc) ? 1.f : 0.f;
            mk.z = (m1.z > 0.f || dm.z > capc) ? 1.f : 0.f;
            mk.w = (m1.w > 0.f || dm.w > capc) ? 1.f : 0.f;
            bool mine = true;
            if (lane < NP4) {
                if (lane > 0) mine = (mk.x > 0.f) && (mk.y > 0.f) && (mk.z > 0.f) && (mk.w > 0.f);
                else          mine = (mk.y > 0.f) && (mk.z > 0.f) && (mk.w > 0.f);
            }
            bool allc = __all_sync(0xffffffffu, mine);
            if (lane == 0) mk.x = allc ? 0.f : ((idx == 0) ? 1.f : 0.f);
            if (lane < NP4) reinterpret_cast<float4*>(MSK)[lane] = mk;
        }
        __syncthreads();
    }

    if (t == 0) out[(size_t)B * ns + b] = misc[2];
}

// =====================================================================
// launch
// =====================================================================
extern "C" void kernel_launch(void* const* d_in, const int* in_sizes, int n_in,
                              void* d_out, int out_size)
{
    const float* enc      = (const float*)d_in[0];
    const float* pool     = (const float*)d_in[1];
    const float* capacity = (const float*)d_in[2];
    const float* demand   = (const float*)d_in[3];
    const float* fc_w     = (const float*)d_in[4];
    const float* fc1_w    = (const float*)d_in[5];
    const float* Wq       = (const float*)d_in[6];
    const float* Wk       = (const float*)d_in[7];
    const float* Wv       = (const float*)d_in[8];
    const float* Wo       = (const float*)d_in[9];
    const float* Wk2      = (const float*)d_in[10];
    const int*   Tptr     = (const int*)d_in[12];

    int B  = in_sizes[0] / (Nn * Hh);          // 1024
    int ns = out_size / B - 1;                 // 128
    float* out = (float*)d_out;

    weights_kernel<<<768, 128>>>(fc_w, fc1_w, Wq, Wk, Wv, Wo, Wk2);
    qpool_kernel<<<B, 128>>>(pool);

    cudaFuncSetAttribute(encproj_kernel, cudaFuncAttributeMaxDynamicSharedMemorySize, Nn * Hh * 4);
    encproj_kernel<<<B, 512, Nn * Hh * 4>>>(enc);

    cudaFuncSetAttribute(decode_kernel, cudaFuncAttributeMaxDynamicSharedMemorySize, DEC_SMEM_BYTES);
    decode_kernel<<<B, 512, DEC_SMEM_BYTES>>>(capacity, demand, Tptr, out, ns, B);
}

// round 13
// speedup vs baseline: 1.5384x; 1.5384x over previous
#include <cuda_runtime.h>
#include <math.h>

#define Bmax 1024
#define Nn   100
#define Hh   128
#define NHEADS 8
#define HD   16
#define KTS  104        // KT stride (floats) = 26 f4
#define VTS  108        // VT stride = 27 f4 (odd f4 -> conflict-free row-per-lane)
#define K2S  132        // K2 stride = 33 f4 (odd f4)
#define NP4  26
#define NPF  104
#define NEGV -1000000000.0f

// ---- device scratch ----
__device__ float g_Wcat[Hh * 512];
__device__ float g_Wqf [Hh * (Hh + 1)];
__device__ float g_Wq1 [Hh * Hh];
__device__ float g_qpool[Bmax * Hh];
__device__ float g_EncProj[(size_t)Bmax * 256 * Nn];   // [b][j][n]: K | V
__device__ float g_K2Wt[(size_t)Bmax * Nn * Hh];       // [b][n][h]
__device__ float g_QP  [(size_t)Bmax * Nn * Hh];       // [b][n][h]

// =====================================================================
__global__ void weights_kernel(const float* __restrict__ fc_w,
                               const float* __restrict__ fc1_w,
                               const float* __restrict__ Wq,
                               const float* __restrict__ Wk,
                               const float* __restrict__ Wv,
                               const float* __restrict__ Wo,
                               const float* __restrict__ Wk2)
{
    int bid = blockIdx.x, t = threadIdx.x;
    if (bid < 512) {
        int j = bid;
        float v;
        if (j < 128) {
            v = Wk[j * 128 + t];
        } else if (j < 256) {
            v = Wv[(j - 128) * 128 + t];
        } else if (j < 384) {
            int jp = j - 256;
            float s = 0.f;
            for (int h = 0; h < 128; h++) s += Wk2[h * 128 + t] * Wo[h * 128 + jp];
            v = s;
        } else {
            int hq = j - 384;
            float s = 0.f;
            for (int jj = 0; jj < 128; jj++) s += Wq[hq * 128 + jj] * fc_w[jj * 129 + t];
            v = s;
        }
        g_Wcat[t * 512 + j] = v;
    } else if (bid < 640) {
        int i = bid - 512;
        for (int k = t; k < 129; k += 128) {
            float s = 0.f;
            for (int j = 0; j < 128; j++) s += Wq[i * 128 + j] * fc_w[j * 129 + k];
            g_Wqf[i * 129 + k] = s;
        }
    } else {
        int i = bid - 640;
        float s = 0.f;
        for (int j = 0; j < 128; j++) s += Wq[i * 128 + j] * fc1_w[j * 128 + t];
        g_Wq1[i * 128 + t] = s;
    }
}

// =====================================================================
__global__ void qpool_kernel(const float* __restrict__ pool)
{
    int b = blockIdx.x, h = threadIdx.x;
    float s = 0.f;
    for (int k = 0; k < 128; k++) s += g_Wq1[h * 128 + k] * pool[b * 128 + k];
    g_qpool[b * 128 + h] = s;
}

// =====================================================================
__global__ __launch_bounds__(512, 1)
void encproj_kernel(const float* __restrict__ enc)
{
    extern __shared__ float As[];
    int b = blockIdx.x, t = threadIdx.x;
    for (int i = t; i < Nn * Hh; i += 512) As[i] = enc[(size_t)b * Nn * Hh + i];
    float w[128];
#pragma unroll
    for (int k = 0; k < 128; k++) w[k] = g_Wcat[k * 512 + t];
    __syncthreads();

    float* rowp = (t < 256) ? (g_EncProj + (size_t)b * 256 * Nn + (size_t)t * Nn) : 0;
    float* colp = (t < 384) ? (g_K2Wt + (size_t)b * Nn * Hh + (t - 256))
                            : (g_QP   + (size_t)b * Nn * Hh + (t - 384));

    for (int n0 = 0; n0 < Nn; n0 += 4) {
        float a0 = 0.f, a1 = 0.f, a2 = 0.f, a3 = 0.f;
        const float4* r0 = reinterpret_cast<const float4*>(&As[(n0 + 0) * Hh]);
        const float4* r1 = reinterpret_cast<const float4*>(&As[(n0 + 1) * Hh]);
        const float4* r2 = reinterpret_cast<const float4*>(&As[(n0 + 2) * Hh]);
        const float4* r3 = reinterpret_cast<const float4*>(&As[(n0 + 3) * Hh]);
#pragma unroll
        for (int kk = 0; kk < 32; kk++) {
            float4 x0 = r0[kk];
            a0 += x0.x * w[4*kk] + x0.y * w[4*kk+1] + x0.z * w[4*kk+2] + x0.w * w[4*kk+3];
            float4 x1 = r1[kk];
            a1 += x1.x * w[4*kk] + x1.y * w[4*kk+1] + x1.z * w[4*kk+2] + x1.w * w[4*kk+3];
            float4 x2 = r2[kk];
            a2 += x2.x * w[4*kk] + x2.y * w[4*kk+1] + x2.z * w[4*kk+2] + x2.w * w[4*kk+3];
            float4 x3 = r3[kk];
            a3 += x3.x * w[4*kk] + x3.y * w[4*kk+1] + x3.z * w[4*kk+2] + x3.w * w[4*kk+3];
        }
        if (t < 256) {
            reinterpret_cast<float4*>(rowp + n0)[0] = make_float4(a0, a1, a2, a3);
        } else {
            colp[(size_t)(n0 + 0) * Hh] = a0;
            colp[(size_t)(n0 + 1) * Hh] = a1;
            colp[(size_t)(n0 + 2) * Hh] = a2;
            colp[(size_t)(n0 + 3) * Hh] = a3;
        }
    }
}

// =====================================================================
// Kernel 4: dense, conflict-free vectorized decoder. 512 thr, 1 blk/SM.
// =====================================================================
#define DEC_SMEM_FLOATS (Hh*KTS + Hh*VTS + Nn*K2S + Nn*Hh + 128 + 128 + NHEADS*NPF + 128 + NPF + NPF + NPF + NPF + 16)
#define DEC_SMEM_BYTES  (DEC_SMEM_FLOATS * 4)

__global__ __launch_bounds__(512, 1)
void decode_kernel(const float* __restrict__ capacity,
                   const float* __restrict__ demand,
                   const int*   __restrict__ Tptr,
                   float* __restrict__ out, int ns, int B)
{
    extern __shared__ float sm[];
    float* KT    = sm;                    // [128][104]
    float* VT    = KT   + Hh * KTS;       // [128][108]
    float* K2s   = VT   + Hh * VTS;       // [100][132]
    float* QPs   = K2s  + Nn * K2S;       // [100][128]
    float* qp    = QPs  + Nn * Hh;        // 128
    float* wcap  = qp   + 128;            // 128
    float* att   = wcap + 128;            // [8][104]
    float* g     = att  + NHEADS * NPF;   // 128
    float* u     = g    + 128;            // 104
    float* dem   = u    + NPF;            // 104
    float* mask1 = dem  + NPF;            // 104
    float* MSK   = mask1+ NPF;            // 104
    float* misc  = MSK  + NPF;            // [0]=cap [1]=base [2]=logp [3]=invT
    int*   imisc = (int*)(misc + 8);      // [0]=idx [1]=visited

    const int b = blockIdx.x, t = threadIdx.x;
    const int w = t >> 5, lane = t & 31;

    // ---- load operands ----
    const float* ep = g_EncProj + (size_t)b * 256 * Nn;
    for (int i = t; i < 128 * KTS; i += 512) {           // KT
        int j = i / KTS, n = i - j * KTS;
        KT[i] = (n < Nn) ? ep[j * Nn + n] : 0.f;
    }
    for (int i = t; i < 128 * VTS; i += 512) {           // VT
        int j = i / VTS, n = i - j * VTS;
        VT[i] = (n < Nn) ? ep[(128 + j) * Nn + n] : 0.f;
    }
    const float* k2g = g_K2Wt + (size_t)b * Nn * Hh;
    for (int i = t; i < Nn * K2S; i += 512) {            // K2 rows
        int n = i / K2S, h = i - n * K2S;
        K2s[i] = (h < Hh) ? k2g[n * Hh + h] : 0.f;
    }
    const float* qpg = g_QP + (size_t)b * Nn * Hh;
    for (int i = t; i < Nn * Hh; i += 512) QPs[i] = qpg[i];
    if (t < 128) {
        qp[t]   = g_qpool[b * 128 + t];
        wcap[t] = g_Wqf[t * 129 + 128];
    }
    if (t < NPF) {
        dem[t]   = (t < Nn) ? demand[b * Nn + t] : 3.0e38f;
        mask1[t] = (t < Nn) ? 0.f : 1.f;
        if (t >= Nn) u[t] = NEGV;                         // pad once
    }
    if (t == 0) {
        float c = capacity[b];
        misc[0] = c; misc[1] = capacity[0]; misc[2] = 0.f;
        misc[3] = 1.0f / (float)(*Tptr);
        imisc[0] = 0; imisc[1] = 0;
    }
    __syncthreads();

    // ---- initial mask (idx=0, mask1=0) : warp 0 ----
    if (w == 0) {
        float capc = misc[0];
        const int li = (lane < NP4) ? lane : 0;
        float4 dm = reinterpret_cast<const float4*>(dem)[li];
        float4 m1 = reinterpret_cast<const float4*>(mask1)[li];
        float4 mk;
        mk.x = (m1.x > 0.f || dm.x > capc) ? 1.f : 0.f;
        mk.y = (m1.y > 0.f || dm.y > capc) ? 1.f : 0.f;
        mk.z = (m1.z > 0.f || dm.z > capc) ? 1.f : 0.f;
        mk.w = (m1.w > 0.f || dm.w > capc) ? 1.f : 0.f;
        bool mine = true;
        if (lane < NP4) {
            if (lane > 0) mine = (mk.x > 0.f) && (mk.y > 0.f) && (mk.z > 0.f) && (mk.w > 0.f);
            else          mine = (mk.y > 0.f) && (mk.z > 0.f) && (mk.w > 0.f);
        }
        bool allc = __all_sync(0xffffffffu, mine);
        if (lane == 0) mk.x = allc ? 0.f : 1.f;
        if (lane < NP4) reinterpret_cast<float4*>(MSK)[lane] = mk;
    }
    __syncthreads();

    const float4* KT4  = reinterpret_cast<const float4*>(KT);
    const float4* VT4  = reinterpret_cast<const float4*>(VT);
    const float4* MSK4 = reinterpret_cast<const float4*>(MSK);
    const float4* g4   = reinterpret_cast<const float4*>(g);
    float4* att4 = reinterpret_cast<float4*>(att);

    for (int step = 0; step < ns; step++) {
        // ==== R1: q chunk + dense scores + softmax (warp w = head w) ====
        if (w < NHEADS) {
            int sidx = imisc[0];
            float capc = misc[0];
            float qd = 0.f;
            if (lane < HD) {
                int hh = w * HD + lane;
                qd = qp[hh] + QPs[sidx * Hh + hh] + capc * wcap[hh];
            }
            float4 acc = make_float4(0.f, 0.f, 0.f, 0.f);
            const int li = (lane < NP4) ? lane : 0;
            const float4* kb = KT4 + (w * HD) * NP4;
#pragma unroll
            for (int d = 0; d < HD; d++) {
                float qv = __shfl_sync(0xffffffffu, qd, d);
                float4 kv = kb[d * NP4 + li];
                acc.x += qv * kv.x; acc.y += qv * kv.y;
                acc.z += qv * kv.z; acc.w += qv * kv.w;
            }
            float4 mv = MSK4[li];
            float4 v;
            v.x = (lane < NP4 && mv.x == 0.f) ? acc.x * 0.25f : NEGV;
            v.y = (lane < NP4 && mv.y == 0.f) ? acc.y * 0.25f : NEGV;
            v.z = (lane < NP4 && mv.z == 0.f) ? acc.z * 0.25f : NEGV;
            v.w = (lane < NP4 && mv.w == 0.f) ? acc.w * 0.25f : NEGV;
            float m = fmaxf(fmaxf(v.x, v.y), fmaxf(v.z, v.w));
#pragma unroll
            for (int off = 16; off; off >>= 1) m = fmaxf(m, __shfl_xor_sync(0xffffffffu, m, off));
            float4 e;
            e.x = expf(v.x - m); e.y = expf(v.y - m);
            e.z = expf(v.z - m); e.w = expf(v.w - m);
            float ss = e.x + e.y + e.z + e.w;
#pragma unroll
            for (int off = 16; off; off >>= 1) ss += __shfl_xor_sync(0xffffffffu, ss, off);
            float inv = 1.f / ss;
            if (lane < NP4)
                att4[w * NP4 + lane] = make_float4(e.x*inv, e.y*inv, e.z*inv, e.w*inv);
        }
        __syncthreads();

        // ==== R2: g[h] = attn_head(h) · V[h] — one thread per h ====
        if (t < 128) {
            const float4* ap = att4 + (t >> 4) * NP4;    // broadcast (2 addrs/warp)
            const float4* vp = VT4 + t * 27;             // odd f4 stride: conflict-free
            float sg = 0.f;
#pragma unroll
            for (int k = 0; k < NP4; k++) {
                float4 a = ap[k], vv = vp[k];
                sg += a.x*vv.x + a.y*vv.y + a.z*vv.z + a.w*vv.w;
            }
            g[t] = sg;
        }
        __syncthreads();

        // ==== R3: dense u[n]; 4 thr/row with staggered chunk order ====
        {
            int n = t >> 2, p4 = t & 3;
            int nc = (n < Nn) ? n : 0;
            const float4* kp = reinterpret_cast<const float4*>(K2s) + nc * 33 + p4 * 8;
            const float4* gp = g4 + p4 * 8;
            float su = 0.f;
#pragma unroll
            for (int r = 0; r < 8; r++) {
                int rr = (r + 2 * p4) & 7;               // bank stagger
                float4 kv = kp[rr], gv = gp[rr];
                su += kv.x*gv.x + kv.y*gv.y + kv.z*gv.z + kv.w*gv.w;
            }
            su += __shfl_xor_sync(0xffffffffu, su, 1);
            su += __shfl_xor_sync(0xffffffffu, su, 2);
            if (p4 == 0 && n < Nn) {
                u[n] = (MSK[n] == 0.f) ? 10.f * tanhf(su * 0.08838834764831845f) : NEGV;
            }
        }
        __syncthreads();

        // ==== R4: argmax + log-softmax + state + mask update (warp 0) ====
        if (w == 0) {
            float invT = misc[3];
            const int li = (lane < NP4) ? lane : 0;
            float4 uv = reinterpret_cast<const float4*>(u)[li];
            float4 v;
            v.x = (lane < NP4) ? uv.x * invT : NEGV;
            v.y = (lane < NP4) ? uv.y * invT : NEGV;
            v.z = (lane < NP4) ? uv.z * invT : NEGV;
            v.w = (lane < NP4) ? uv.w * invT : NEGV;
            int n0 = lane * 4;
            float best = v.x; int bn = n0;
            if (v.y > best) { best = v.y; bn = n0 + 1; }
            if (v.z > best) { best = v.z; bn = n0 + 2; }
            if (v.w > best) { best = v.w; bn = n0 + 3; }
#pragma unroll
            for (int off = 16; off; off >>= 1) {
                float ov = __shfl_xor_sync(0xffffffffu, best, off);
                int   on = __shfl_xor_sync(0xffffffffu, bn,   off);
                if (ov > best || (ov == best && on < bn)) { best = ov; bn = on; }
            }
            float ss = expf(v.x - best) + expf(v.y - best)
                     + expf(v.z - best) + expf(v.w - best);
#pragma unroll
            for (int off = 16; off; off >>= 1) ss += __shfl_xor_sync(0xffffffffu, ss, off);

            if (lane == 0) {
                int idx = bn;
                imisc[0] = idx;
                if (imisc[1] < Nn - 1) misc[2] += -logf(ss);
                out[(size_t)b * ns + step] = (float)idx;
                float c = (idx == 0) ? misc[1] : misc[0] - dem[idx];
                misc[0] = c;
                if (idx > 0 && mask1[idx] == 0.f) { mask1[idx] = 1.f; imisc[1] += 1; }
            }
            __syncwarp();
            float capc = misc[0];
            int idx = imisc[0];
            float4 dm = reinterpret_cast<const float4*>(dem)[li];
            float4 m1 = reinterpret_cast<const float4*>(mask1)[li];
            float4 mk;
            mk.x = (m1.x > 0.f || dm.x > capc) ? 1.f : 0.f;
            mk.y = (m1.y > 0.f || dm.y > capc) ? 1.f : 0.f;
            mk.z = (m1.z > 0.f || dm.z > capc) ? 1.f : 0.f;
            mk.w = (m1.w > 0.f || dm.w > capc) ? 1.f : 0.f;
            bool mine = true;
            if (lane < NP4) {
                if (lane > 0) mine = (mk.x > 0.f) && (mk.y > 0.f) && (mk.z > 0.f) && (mk.w > 0.f);
                else          mine = (mk.y > 0.f) && (mk.z > 0.f) && (mk.w > 0.f);
            }
            bool allc = __all_sync(0xffffffffu, mine);
            if (lane == 0) mk.x = allc ? 0.f : ((idx == 0) ? 1.f : 0.f);
            if (lane < NP4) reinterpret_cast<float4*>(MSK)[lane] = mk;
        }
        __syncthreads();
    }

    if (t == 0) out[(size_t)B * ns + b] = misc[2];
}

// =====================================================================
extern "C" void kernel_launch(void* const* d_in, const int* in_sizes, int n_in,
                              void* d_out, int out_size)
{
    const float* enc      = (const float*)d_in[0];
    const float* pool     = (const float*)d_in[1];
    const float* capacity = (const float*)d_in[2];
    const float* demand   = (const float*)d_in[3];
    const float* fc_w     = (const float*)d_in[4];
    const float* fc1_w    = (const float*)d_in[5];
    const float* Wq       = (const float*)d_in[6];
    const float* Wk       = (const float*)d_in[7];
    const float* Wv       = (const float*)d_in[8];
    const float* Wo       = (const float*)d_in[9];
    const float* Wk2      = (const float*)d_in[10];
    const int*   Tptr     = (const int*)d_in[12];

    int B  = in_sizes[0] / (Nn * Hh);          // 1024
    int ns = out_size / B - 1;                 // 128
    float* out = (float*)d_out;

    weights_kernel<<<768, 128>>>(fc_w, fc1_w, Wq, Wk, Wv, Wo, Wk2);
    qpool_kernel<<<B, 128>>>(pool);

    cudaFuncSetAttribute(encproj_kernel, cudaFuncAttributeMaxDynamicSharedMemorySize, Nn * Hh * 4);
    encproj_kernel<<<B, 512, Nn * Hh * 4>>>(enc);

    cudaFuncSetAttribute(decode_kernel, cudaFuncAttributeMaxDynamicSharedMemorySize, DEC_SMEM_BYTES);
    decode_kernel<<<B, 512, DEC_SMEM_BYTES>>>(capacity, demand, Tptr, out, ns, B);
}